// round 2
// baseline (speedup 1.0000x reference)
#include <cuda_runtime.h>
#include <math.h>

// ---------------- problem constants ----------------
constexpr int BATCH = 64;
constexpr int ED    = 512;
constexpr int HH    = 28;
constexpr int PIX   = HH * HH;        // 784
constexpr int NPIXT = BATCH * PIX;    // 50176 total pixels
constexpr int NWIN  = BATCH * 16;     // 1024 windows (4x4 of 7x7)
constexpr int WN    = 49;             // pixels per window
constexpr int NH    = 8;
constexpr int KD    = 16;
constexpr int DV    = 64;             // AR*KD
constexpr int QKVO  = 2 * KD + DV;    // 96

// ---------------- scratch (no allocs allowed) ----------------
__device__ float g_bufA[BATCH * ED * PIX];
__device__ float g_bufB[BATCH * ED * PIX];
__device__ float g_bufC[BATCH * ED * PIX];
__device__ float g_bufD[BATCH * ED * PIX];
__device__ float g_bufH[BATCH * 2 * ED * PIX];
__device__ float g_bufW[NWIN * ED * WN];

// ---------------- depthwise 3x3 + residual ----------------
__global__ void dwconv_res_kernel(const float* __restrict__ x,
                                  const float* __restrict__ w,
                                  const float* __restrict__ bias,
                                  float* __restrict__ out) {
    int idx = blockIdx.x * blockDim.x + threadIdx.x;
    if (idx >= BATCH * ED * PIX) return;
    int hw = idx % PIX;
    int c  = (idx / PIX) % ED;
    int h  = hw / HH, col = hw % HH;
    const float* wp = w + c * 9;
    const float* xp = x + (idx - hw);   // plane base
    float acc = bias[c];
#pragma unroll
    for (int dy = 0; dy < 3; dy++) {
        int hh = h + dy - 1;
        if (hh < 0 || hh >= HH) continue;
#pragma unroll
        for (int dx = 0; dx < 3; dx++) {
            int ww = col + dx - 1;
            if (ww < 0 || ww >= HH) continue;
            acc += wp[dy * 3 + dx] * xp[hh * HH + ww];
        }
    }
    out[idx] = x[idx] + acc;
}

// ---------------- tiled SGEMM: out[o,p] = W[o,:] . act[:,p] ----------------
// ACT_MODE 0: act in [B, K, 784] layout (pixel p -> b=p/784, hw=p%784)
// ACT_MODE 1: act in [win, K, 49] layout (p -> w=p/49, n=p%49)
// EPI 0: out = hardswish(acc+bias)      -> [B, M, 784]
// EPI 1: out = res + acc + bias         -> [B, M, 784]
// EPI 2: out = res + acc + bias with window-merge indexing -> [B, 512, 784]
template <int ACT_MODE, int EPI>
__global__ void __launch_bounds__(256)
gemm_kernel(const float* __restrict__ W, const float* __restrict__ bias,
            const float* __restrict__ act, const float* __restrict__ res,
            float* __restrict__ out, int M, int K) {
    __shared__ float As[16][128];
    __shared__ float Bs[16][128];
    __shared__ int   colBase[128];

    int tid = threadIdx.x;
    int tx = tid & 15, ty = tid >> 4;
    int m0 = blockIdx.y * 128, n0 = blockIdx.x * 128;
    const int kstride = (ACT_MODE == 0) ? PIX : WN;

    if (tid < 128) {
        int p = n0 + tid;
        if (ACT_MODE == 0) {
            int b = p / PIX, hw = p % PIX;
            colBase[tid] = b * K * PIX + hw;
        } else {
            int w = p / WN, n = p % WN;
            colBase[tid] = w * K * WN + n;
        }
    }
    __syncthreads();

    float acc[8][8];
#pragma unroll
    for (int i = 0; i < 8; i++)
#pragma unroll
        for (int j = 0; j < 8; j++) acc[i][j] = 0.f;

    for (int k0 = 0; k0 < K; k0 += 16) {
        // A tile: 128 rows x 16 k  (transposed store)
#pragma unroll
        for (int r = 0; r < 2; r++) {
            int f = tid + r * 256;       // 0..511 float4s
            int row = f >> 2;
            int kq = (f & 3) * 4;
            float4 v = *(const float4*)&W[(size_t)(m0 + row) * K + k0 + kq];
            As[kq + 0][row] = v.x;
            As[kq + 1][row] = v.y;
            As[kq + 2][row] = v.z;
            As[kq + 3][row] = v.w;
        }
        // B tile: 16 k x 128 cols
        {
            int n = tid & 127;
            int kk0 = (tid >> 7) * 8;
            int base = colBase[n] + (k0 + kk0) * kstride;
#pragma unroll
            for (int kk = 0; kk < 8; kk++)
                Bs[kk0 + kk][n] = act[base + kk * kstride];
        }
        __syncthreads();
#pragma unroll
        for (int kk = 0; kk < 16; kk++) {
            float ra[8], rb[8];
            float4 a0 = *(const float4*)&As[kk][ty * 8];
            float4 a1 = *(const float4*)&As[kk][ty * 8 + 4];
            float4 b0 = *(const float4*)&Bs[kk][tx * 8];
            float4 b1 = *(const float4*)&Bs[kk][tx * 8 + 4];
            ra[0] = a0.x; ra[1] = a0.y; ra[2] = a0.z; ra[3] = a0.w;
            ra[4] = a1.x; ra[5] = a1.y; ra[6] = a1.z; ra[7] = a1.w;
            rb[0] = b0.x; rb[1] = b0.y; rb[2] = b0.z; rb[3] = b0.w;
            rb[4] = b1.x; rb[5] = b1.y; rb[6] = b1.z; rb[7] = b1.w;
#pragma unroll
            for (int i = 0; i < 8; i++)
#pragma unroll
                for (int j = 0; j < 8; j++)
                    acc[i][j] += ra[i] * rb[j];
        }
        __syncthreads();
    }

#pragma unroll
    for (int i = 0; i < 8; i++) {
        int m = m0 + ty * 8 + i;
        float bv = bias[m];
#pragma unroll
        for (int j = 0; j < 8; j++) {
            int p = n0 + tx * 8 + j;
            float v = acc[i][j] + bv;
            if (EPI == 0) {
                float t = fminf(fmaxf(v + 3.f, 0.f), 6.f);
                v = v * t * (1.f / 6.f);
                int b = p / PIX, hw = p % PIX;
                out[(size_t)(b * M + m) * PIX + hw] = v;
            } else if (EPI == 1) {
                int b = p / PIX, hw = p % PIX;
                size_t idx = (size_t)(b * M + m) * PIX + hw;
                out[idx] = res[idx] + v;
            } else {
                int w = p / WN, n = p % WN;
                int b = w >> 4, wh = (w >> 2) & 3, ww = w & 3;
                int gh = wh * 7 + n / 7, gw = ww * 7 + n % 7;
                size_t idx = (size_t)(b * ED + m) * PIX + gh * HH + gw;
                out[idx] = res[idx] + v;
            }
        }
    }
}

// ---------------- cascade window attention ----------------
// one CTA per 7x7 window; 8 heads sequential with sp accumulation.
// writes hardswish(head output) to g_bufW in [win, 512, 49] layout.
__global__ void __launch_bounds__(256)
attn_kernel(const float* __restrict__ x2,
            const float* __restrict__ qkv_w, const float* __restrict__ qkv_b,
            const float* __restrict__ dwq_w7, const float* __restrict__ dwq_b7,
            const float* __restrict__ dwq_w5, const float* __restrict__ dwq_b5,
            const float* __restrict__ dwq_w3, const float* __restrict__ dwq_b3,
            const float* __restrict__ attn_bias,
            float* __restrict__ outw) {
    extern __shared__ float sm[];
    float* sp   = sm;                 // 64*49
    float* qkvw = sp + DV * WN;       // 96*64
    float* qkvb = qkvw + QKVO * 64;   // 96
    float* qs   = qkvb + QKVO;        // 16*49
    float* ks_  = qs + KD * WN;       // 16*49
    float* vs   = ks_ + KD * WN;      // 64*49
    float* qc   = vs + DV * WN;       // 16*49
    float* at   = qc + KD * WN;       // 49*49
    float* bs   = at + WN * WN;       // 49

    int wdx = blockIdx.x;             // 0..1023
    int b = wdx >> 4, wh = (wdx >> 2) & 3, ww = wdx & 3;
    int tid = threadIdx.x;
    int gbase = b * ED * PIX + (wh * 7) * HH + ww * 7;

    for (int head = 0; head < NH; head++) {
        // load per-head weights
        for (int t = tid; t < QKVO * 64; t += 256) qkvw[t] = qkv_w[head * QKVO * 64 + t];
        if (tid < QKVO) qkvb[tid] = qkv_b[head * QKVO + tid];
        if (tid < WN)   bs[tid]   = attn_bias[head * WN + tid];
        // sp accumulate (cascade)
        for (int t = tid; t < DV * WN; t += 256) {
            int c = t / WN, n = t % WN;
            float v = x2[gbase + (head * DV + c) * PIX + (n / 7) * HH + (n % 7)];
            sp[t] = (head == 0) ? v : sp[t] + v;
        }
        __syncthreads();
        // qkv: 96x49, K=64
        for (int t = tid; t < QKVO * WN; t += 256) {
            int o = t / WN, n = t % WN;
            float a = qkvb[o];
            const float* wr = &qkvw[o * 64];
#pragma unroll 16
            for (int c = 0; c < 64; c++) a += wr[c] * sp[c * WN + n];
            if (o < KD)           qs[o * WN + n] = a;
            else if (o < 2 * KD)  ks_[(o - KD) * WN + n] = a;
            else                  vs[(o - 2 * KD) * WN + n] = a;
        }
        __syncthreads();
        // depthwise conv on q (ks = 7,5,3,3,...)
        int ksz;
        const float *dw, *db;
        if (head == 0)      { ksz = 7; dw = dwq_w7; db = dwq_b7; }
        else if (head == 1) { ksz = 5; dw = dwq_w5; db = dwq_b5; }
        else                { ksz = 3; dw = dwq_w3 + (head - 2) * KD * 9; db = dwq_b3 + (head - 2) * KD; }
        int pad = ksz / 2;
        for (int t = tid; t < KD * WN; t += 256) {
            int ch = t / WN, n = t % WN;
            int r = n / 7, c = n % 7;
            float a = db[ch];
            for (int dy = 0; dy < ksz; dy++) {
                int rr = r + dy - pad;
                if (rr < 0 || rr >= 7) continue;
                for (int dx = 0; dx < ksz; dx++) {
                    int cc = c + dx - pad;
                    if (cc < 0 || cc >= 7) continue;
                    a += dw[ch * ksz * ksz + dy * ksz + dx] * qs[ch * WN + rr * 7 + cc];
                }
            }
            qc[t] = a;
        }
        __syncthreads();
        // scores: attn[n][m] = 0.25*qc(:,n).k(:,m) + bias[|dr|*7+|dc|]
        for (int t = tid; t < WN * WN; t += 256) {
            int n = t / WN, m = t % WN;
            float a = 0.f;
#pragma unroll
            for (int ch = 0; ch < KD; ch++) a += qc[ch * WN + n] * ks_[ch * WN + m];
            int rn = n / 7, cn = n % 7, rm = m / 7, cm = m % 7;
            at[t] = a * 0.25f + bs[abs(rn - rm) * 7 + abs(cn - cm)];
        }
        __syncthreads();
        // softmax rows
        if (tid < WN) {
            float* row = &at[tid * WN];
            float mx = row[0];
            for (int m = 1; m < WN; m++) mx = fmaxf(mx, row[m]);
            float s = 0.f;
            for (int m = 0; m < WN; m++) { float e = __expf(row[m] - mx); row[m] = e; s += e; }
            float inv = 1.f / s;
            for (int m = 0; m < WN; m++) row[m] *= inv;
        }
        __syncthreads();
        // out[d][n] = sum_m v[d][m]*attn[n][m]; sp <- out; gmem <- hardswish(out)
        for (int t = tid; t < DV * WN; t += 256) {
            int d = t / WN, n = t % WN;
            float a = 0.f;
#pragma unroll 7
            for (int m = 0; m < WN; m++) a += vs[d * WN + m] * at[n * WN + m];
            sp[t] = a;
            float h = a * fminf(fmaxf(a + 3.f, 0.f), 6.f) * (1.f / 6.f);
            outw[((size_t)wdx * ED + head * DV + d) * WN + n] = h;
        }
        __syncthreads();
    }
}

// ---------------- launch ----------------
extern "C" void kernel_launch(void* const* d_in, const int* in_sizes, int n_in,
                              void* d_out, int out_size) {
    const float* x       = (const float*)d_in[0];
    const float* dw0_w   = (const float*)d_in[1];
    const float* dw0_b   = (const float*)d_in[2];
    const float* ffn0_w1 = (const float*)d_in[3];
    const float* ffn0_b1 = (const float*)d_in[4];
    const float* ffn0_w2 = (const float*)d_in[5];
    const float* ffn0_b2 = (const float*)d_in[6];
    const float* qkv_w   = (const float*)d_in[7];
    const float* qkv_b   = (const float*)d_in[8];
    const float* dwq_w7  = (const float*)d_in[9];
    const float* dwq_b7  = (const float*)d_in[10];
    const float* dwq_w5  = (const float*)d_in[11];
    const float* dwq_b5  = (const float*)d_in[12];
    const float* dwq_w3  = (const float*)d_in[13];
    const float* dwq_b3  = (const float*)d_in[14];
    const float* attn_b  = (const float*)d_in[15];
    const float* proj_w  = (const float*)d_in[16];
    const float* proj_b  = (const float*)d_in[17];
    const float* dw1_w   = (const float*)d_in[18];
    const float* dw1_b   = (const float*)d_in[19];
    const float* ffn1_w1 = (const float*)d_in[20];
    const float* ffn1_b1 = (const float*)d_in[21];
    const float* ffn1_w2 = (const float*)d_in[22];
    const float* ffn1_b2 = (const float*)d_in[23];
    float* out = (float*)d_out;

    float *pA, *pB, *pC, *pD, *pH, *pW;
    cudaGetSymbolAddress((void**)&pA, g_bufA);
    cudaGetSymbolAddress((void**)&pB, g_bufB);
    cudaGetSymbolAddress((void**)&pC, g_bufC);
    cudaGetSymbolAddress((void**)&pD, g_bufD);
    cudaGetSymbolAddress((void**)&pH, g_bufH);
    cudaGetSymbolAddress((void**)&pW, g_bufW);

    const int total = BATCH * ED * PIX;
    const int eb = (total + 255) / 256;
    const dim3 gN392_8(392, 8), gN392_4(392, 4);

    // x1 = x + dw0(x)
    dwconv_res_kernel<<<eb, 256>>>(x, dw0_w, dw0_b, pA);
    // ffn0
    gemm_kernel<0, 0><<<gN392_8, 256>>>(ffn0_w1, ffn0_b1, pA, nullptr, pH, 1024, 512);
    gemm_kernel<0, 1><<<gN392_4, 256>>>(ffn0_w2, ffn0_b2, pH, pA, pB, 512, 1024);
    // cascade attention on windows of x2 (=pB)
    int smem = (DV * WN + QKVO * 64 + QKVO + KD * WN * 3 + DV * WN + WN * WN + WN) * 4;
    cudaFuncSetAttribute(attn_kernel, cudaFuncAttributeMaxDynamicSharedMemorySize, smem);
    attn_kernel<<<NWIN, 256, smem>>>(pB, qkv_w, qkv_b, dwq_w7, dwq_b7, dwq_w5,
                                     dwq_b5, dwq_w3, dwq_b3, attn_b, pW);
    // proj + window merge + residual
    gemm_kernel<1, 2><<<gN392_4, 256>>>(proj_w, proj_b, pW, pB, pC, 512, 512);
    // x4 = x3 + dw1(x3)
    dwconv_res_kernel<<<eb, 256>>>(pC, dw1_w, dw1_b, pD);
    // ffn1 -> d_out
    gemm_kernel<0, 0><<<gN392_8, 256>>>(ffn1_w1, ffn1_b1, pD, nullptr, pH, 1024, 512);
    gemm_kernel<0, 1><<<gN392_4, 256>>>(ffn1_w2, ffn1_b2, pH, pD, out, 512, 1024);
}

// round 3
// speedup vs baseline: 2.0765x; 2.0765x over previous
#include <cuda_runtime.h>
#include <cstdint>
#include <math.h>

// ---------------- problem constants ----------------
constexpr int BATCH = 64;
constexpr int ED    = 512;
constexpr int HH    = 28;
constexpr int PIX   = HH * HH;        // 784
constexpr int NWIN  = BATCH * 16;     // 1024 windows
constexpr int WN    = 49;
constexpr int NH    = 8;
constexpr int KD    = 16;
constexpr int DV    = 64;
constexpr int QKVO  = 2 * KD + DV;    // 96

// ---------------- scratch ----------------
__device__ float g_bufA[BATCH * ED * PIX];
__device__ float g_bufB[BATCH * ED * PIX];
__device__ float g_bufC[BATCH * ED * PIX];
__device__ float g_bufD[BATCH * ED * PIX];
__device__ float g_bufH[BATCH * 2 * ED * PIX];
__device__ float g_bufW[NWIN * ED * WN];

// ---------------- depthwise 3x3 + residual ----------------
__global__ void dwconv_res_kernel(const float* __restrict__ x,
                                  const float* __restrict__ w,
                                  const float* __restrict__ bias,
                                  float* __restrict__ out) {
    int idx = blockIdx.x * blockDim.x + threadIdx.x;
    if (idx >= BATCH * ED * PIX) return;
    int hw = idx % PIX;
    int c  = (idx / PIX) % ED;
    int h  = hw / HH, col = hw % HH;
    const float* wp = w + c * 9;
    const float* xp = x + (idx - hw);
    float acc = bias[c];
#pragma unroll
    for (int dy = 0; dy < 3; dy++) {
        int hh = h + dy - 1;
        if (hh < 0 || hh >= HH) continue;
#pragma unroll
        for (int dx = 0; dx < 3; dx++) {
            int ww = col + dx - 1;
            if (ww < 0 || ww >= HH) continue;
            acc += wp[dy * 3 + dx] * xp[hh * HH + ww];
        }
    }
    out[idx] = x[idx] + acc;
}

// ---------------- tf32 helpers ----------------
__device__ __forceinline__ uint32_t cvt_tf32(float f) {
    uint32_t u;
    asm("cvt.rna.tf32.f32 %0, %1;" : "=r"(u) : "f"(f));
    return u;
}
__device__ __forceinline__ void mma8(float* c, const uint32_t* a, const uint32_t* b) {
    asm volatile(
        "mma.sync.aligned.m16n8k8.row.col.f32.tf32.tf32.f32 "
        "{%0,%1,%2,%3}, {%4,%5,%6,%7}, {%8,%9}, {%0,%1,%2,%3};\n"
        : "+f"(c[0]), "+f"(c[1]), "+f"(c[2]), "+f"(c[3])
        : "r"(a[0]), "r"(a[1]), "r"(a[2]), "r"(a[3]), "r"(b[0]), "r"(b[1]));
}

// ---------------- tensor-core TF32 GEMM ----------------
// out[m,p] = W[m,:] . act[:,p]  (+bias, epilogue variants)
// ACT_MODE 0: act [B, K, 784]; ACT_MODE 1: act [win, K, 49]
// EPI 0: hardswish -> [B,M,784]; EPI 1: res+v -> [B,M,784];
// EPI 2: res+v with window-merge -> [B,512,784]
template <int ACT_MODE, int EPI>
__global__ void __launch_bounds__(256)
gemm_tc(const float* __restrict__ Wt, const float* __restrict__ bias,
        const float* __restrict__ act, const float* __restrict__ res,
        float* __restrict__ out, int M, int K) {
    __shared__ uint32_t As[128][36];   // [m][k], pad 36 -> conflict-free frags
    __shared__ uint32_t Bs[32][136];   // [k][n], pad 136 -> conflict-free frags

    const int tid  = threadIdx.x;
    const int wid  = tid >> 5, lane = tid & 31;
    const int gid  = lane >> 2, tig = lane & 3;
    const int warp_m = wid & 3, warp_n = wid >> 2;
    const int m0 = blockIdx.y * 128, n0 = blockIdx.x * 128;
    const int kstride = (ACT_MODE == 0) ? PIX : WN;

    // B load column for this thread
    const int nloc = tid & 127;
    int colBase;
    {
        int p = n0 + nloc;
        if (ACT_MODE == 0) { int b = p / PIX, hw = p % PIX; colBase = b * K * PIX + hw; }
        else               { int w = p / WN,  n = p % WN;   colBase = w * K * WN + n; }
    }
    const int kb0 = (tid >> 7) * 16;   // 0 or 16

    // A load rows
    const int arow = tid >> 3;         // 0..31
    const int aq   = (tid & 7) * 4;    // k offset 0..28

    float4 pa[4];
    float  pb[16];
#pragma unroll
    for (int i = 0; i < 4; i++)
        pa[i] = *(const float4*)&Wt[(size_t)(m0 + arow + i * 32) * K + aq];
#pragma unroll
    for (int i = 0; i < 16; i++)
        pb[i] = act[colBase + (kb0 + i) * kstride];

    float c[2][8][4];
#pragma unroll
    for (int a = 0; a < 2; a++)
#pragma unroll
        for (int b = 0; b < 8; b++)
#pragma unroll
            for (int q = 0; q < 4; q++) c[a][b][q] = 0.f;

    const int nk = K / 32;
    for (int kt = 0; kt < nk; kt++) {
        // stage prefetched tile into SMEM (tf32-converted)
#pragma unroll
        for (int i = 0; i < 4; i++) {
            uint4 v;
            v.x = cvt_tf32(pa[i].x); v.y = cvt_tf32(pa[i].y);
            v.z = cvt_tf32(pa[i].z); v.w = cvt_tf32(pa[i].w);
            *(uint4*)&As[arow + i * 32][aq] = v;
        }
#pragma unroll
        for (int i = 0; i < 16; i++)
            Bs[kb0 + i][nloc] = cvt_tf32(pb[i]);
        __syncthreads();

        // prefetch next tile
        if (kt + 1 < nk) {
            int k0 = (kt + 1) * 32;
#pragma unroll
            for (int i = 0; i < 4; i++)
                pa[i] = *(const float4*)&Wt[(size_t)(m0 + arow + i * 32) * K + k0 + aq];
#pragma unroll
            for (int i = 0; i < 16; i++)
                pb[i] = act[colBase + (k0 + kb0 + i) * kstride];
        }

        // compute: 4 k8 steps
#pragma unroll
        for (int kk = 0; kk < 4; kk++) {
            const int kr = kk * 8;
            uint32_t afr[2][4], bfr[8][2];
#pragma unroll
            for (int mt = 0; mt < 2; mt++) {
                int mb = warp_m * 32 + mt * 16;
                afr[mt][0] = As[mb + gid][kr + tig];
                afr[mt][1] = As[mb + gid + 8][kr + tig];
                afr[mt][2] = As[mb + gid][kr + tig + 4];
                afr[mt][3] = As[mb + gid + 8][kr + tig + 4];
            }
#pragma unroll
            for (int nt = 0; nt < 8; nt++) {
                int nb = warp_n * 64 + nt * 8;
                bfr[nt][0] = Bs[kr + tig][nb + gid];
                bfr[nt][1] = Bs[kr + tig + 4][nb + gid];
            }
#pragma unroll
            for (int mt = 0; mt < 2; mt++)
#pragma unroll
                for (int nt = 0; nt < 8; nt++)
                    mma8(c[mt][nt], afr[mt], bfr[nt]);
        }
        __syncthreads();
    }

    // ---------------- epilogue ----------------
#pragma unroll
    for (int mt = 0; mt < 2; mt++) {
        const int mr0 = m0 + warp_m * 32 + mt * 16 + gid;
        const float bv0 = __ldg(&bias[mr0]);
        const float bv1 = __ldg(&bias[mr0 + 8]);
#pragma unroll
        for (int nt = 0; nt < 8; nt++) {
            const int pc = n0 + warp_n * 64 + nt * 8 + tig * 2;
#pragma unroll
            for (int q = 0; q < 4; q++) {
                const int m = (q < 2) ? mr0 : mr0 + 8;
                const float bv = (q < 2) ? bv0 : bv1;
                const int p = pc + (q & 1);
                float v = c[mt][nt][q] + bv;
                if (EPI == 0) {
                    float t = fminf(fmaxf(v + 3.f, 0.f), 6.f);
                    v = v * t * (1.f / 6.f);
                    int b = p / PIX, hw = p % PIX;
                    out[(size_t)(b * M + m) * PIX + hw] = v;
                } else if (EPI == 1) {
                    int b = p / PIX, hw = p % PIX;
                    size_t idx = (size_t)(b * M + m) * PIX + hw;
                    out[idx] = res[idx] + v;
                } else {
                    int w = p / WN, n = p % WN;
                    int b = w >> 4, wh = (w >> 2) & 3, ww = w & 3;
                    int gh = wh * 7 + n / 7, gw = ww * 7 + n % 7;
                    size_t idx = (size_t)(b * ED + m) * PIX + gh * HH + gw;
                    out[idx] = res[idx] + v;
                }
            }
        }
    }
}

// ---------------- cascade window attention (unchanged) ----------------
__global__ void __launch_bounds__(256)
attn_kernel(const float* __restrict__ x2,
            const float* __restrict__ qkv_w, const float* __restrict__ qkv_b,
            const float* __restrict__ dwq_w7, const float* __restrict__ dwq_b7,
            const float* __restrict__ dwq_w5, const float* __restrict__ dwq_b5,
            const float* __restrict__ dwq_w3, const float* __restrict__ dwq_b3,
            const float* __restrict__ attn_bias,
            float* __restrict__ outw) {
    extern __shared__ float sm[];
    float* sp   = sm;
    float* qkvw = sp + DV * WN;
    float* qkvb = qkvw + QKVO * 64;
    float* qs   = qkvb + QKVO;
    float* ks_  = qs + KD * WN;
    float* vs   = ks_ + KD * WN;
    float* qc   = vs + DV * WN;
    float* at   = qc + KD * WN;
    float* bs   = at + WN * WN;

    int wdx = blockIdx.x;
    int b = wdx >> 4, wh = (wdx >> 2) & 3, ww = wdx & 3;
    int tid = threadIdx.x;
    int gbase = b * ED * PIX + (wh * 7) * HH + ww * 7;

    for (int head = 0; head < NH; head++) {
        for (int t = tid; t < QKVO * 64; t += 256) qkvw[t] = qkv_w[head * QKVO * 64 + t];
        if (tid < QKVO) qkvb[tid] = qkv_b[head * QKVO + tid];
        if (tid < WN)   bs[tid]   = attn_bias[head * WN + tid];
        for (int t = tid; t < DV * WN; t += 256) {
            int c = t / WN, n = t % WN;
            float v = x2[gbase + (head * DV + c) * PIX + (n / 7) * HH + (n % 7)];
            sp[t] = (head == 0) ? v : sp[t] + v;
        }
        __syncthreads();
        for (int t = tid; t < QKVO * WN; t += 256) {
            int o = t / WN, n = t % WN;
            float a = qkvb[o];
            const float* wr = &qkvw[o * 64];
#pragma unroll 16
            for (int c = 0; c < 64; c++) a += wr[c] * sp[c * WN + n];
            if (o < KD)           qs[o * WN + n] = a;
            else if (o < 2 * KD)  ks_[(o - KD) * WN + n] = a;
            else                  vs[(o - 2 * KD) * WN + n] = a;
        }
        __syncthreads();
        int ksz;
        const float *dw, *db;
        if (head == 0)      { ksz = 7; dw = dwq_w7; db = dwq_b7; }
        else if (head == 1) { ksz = 5; dw = dwq_w5; db = dwq_b5; }
        else                { ksz = 3; dw = dwq_w3 + (head - 2) * KD * 9; db = dwq_b3 + (head - 2) * KD; }
        int pad = ksz / 2;
        for (int t = tid; t < KD * WN; t += 256) {
            int ch = t / WN, n = t % WN;
            int r = n / 7, c = n % 7;
            float a = db[ch];
            for (int dy = 0; dy < ksz; dy++) {
                int rr = r + dy - pad;
                if (rr < 0 || rr >= 7) continue;
                for (int dx = 0; dx < ksz; dx++) {
                    int cc = c + dx - pad;
                    if (cc < 0 || cc >= 7) continue;
                    a += dw[ch * ksz * ksz + dy * ksz + dx] * qs[ch * WN + rr * 7 + cc];
                }
            }
            qc[t] = a;
        }
        __syncthreads();
        for (int t = tid; t < WN * WN; t += 256) {
            int n = t / WN, m = t % WN;
            float a = 0.f;
#pragma unroll
            for (int ch = 0; ch < KD; ch++) a += qc[ch * WN + n] * ks_[ch * WN + m];
            int rn = n / 7, cn = n % 7, rm = m / 7, cm = m % 7;
            at[t] = a * 0.25f + bs[abs(rn - rm) * 7 + abs(cn - cm)];
        }
        __syncthreads();
        if (tid < WN) {
            float* row = &at[tid * WN];
            float mx = row[0];
            for (int m = 1; m < WN; m++) mx = fmaxf(mx, row[m]);
            float s = 0.f;
            for (int m = 0; m < WN; m++) { float e = __expf(row[m] - mx); row[m] = e; s += e; }
            float inv = 1.f / s;
            for (int m = 0; m < WN; m++) row[m] *= inv;
        }
        __syncthreads();
        for (int t = tid; t < DV * WN; t += 256) {
            int d = t / WN, n = t % WN;
            float a = 0.f;
#pragma unroll 7
            for (int m = 0; m < WN; m++) a += vs[d * WN + m] * at[n * WN + m];
            sp[t] = a;
            float h = a * fminf(fmaxf(a + 3.f, 0.f), 6.f) * (1.f / 6.f);
            outw[((size_t)wdx * ED + head * DV + d) * WN + n] = h;
        }
        __syncthreads();
    }
}

// ---------------- launch ----------------
extern "C" void kernel_launch(void* const* d_in, const int* in_sizes, int n_in,
                              void* d_out, int out_size) {
    const float* x       = (const float*)d_in[0];
    const float* dw0_w   = (const float*)d_in[1];
    const float* dw0_b   = (const float*)d_in[2];
    const float* ffn0_w1 = (const float*)d_in[3];
    const float* ffn0_b1 = (const float*)d_in[4];
    const float* ffn0_w2 = (const float*)d_in[5];
    const float* ffn0_b2 = (const float*)d_in[6];
    const float* qkv_w   = (const float*)d_in[7];
    const float* qkv_b   = (const float*)d_in[8];
    const float* dwq_w7  = (const float*)d_in[9];
    const float* dwq_b7  = (const float*)d_in[10];
    const float* dwq_w5  = (const float*)d_in[11];
    const float* dwq_b5  = (const float*)d_in[12];
    const float* dwq_w3  = (const float*)d_in[13];
    const float* dwq_b3  = (const float*)d_in[14];
    const float* attn_b  = (const float*)d_in[15];
    const float* proj_w  = (const float*)d_in[16];
    const float* proj_b  = (const float*)d_in[17];
    const float* dw1_w   = (const float*)d_in[18];
    const float* dw1_b   = (const float*)d_in[19];
    const float* ffn1_w1 = (const float*)d_in[20];
    const float* ffn1_b1 = (const float*)d_in[21];
    const float* ffn1_w2 = (const float*)d_in[22];
    const float* ffn1_b2 = (const float*)d_in[23];
    float* out = (float*)d_out;

    float *pA, *pB, *pC, *pD, *pH, *pW;
    cudaGetSymbolAddress((void**)&pA, g_bufA);
    cudaGetSymbolAddress((void**)&pB, g_bufB);
    cudaGetSymbolAddress((void**)&pC, g_bufC);
    cudaGetSymbolAddress((void**)&pD, g_bufD);
    cudaGetSymbolAddress((void**)&pH, g_bufH);
    cudaGetSymbolAddress((void**)&pW, g_bufW);

    const int total = BATCH * ED * PIX;
    const int eb = (total + 255) / 256;
    const dim3 gN392_8(392, 8), gN392_4(392, 4);

    dwconv_res_kernel<<<eb, 256>>>(x, dw0_w, dw0_b, pA);
    gemm_tc<0, 0><<<gN392_8, 256>>>(ffn0_w1, ffn0_b1, pA, nullptr, pH, 1024, 512);
    gemm_tc<0, 1><<<gN392_4, 256>>>(ffn0_w2, ffn0_b2, pH, pA, pB, 512, 1024);

    int smem = (DV * WN + QKVO * 64 + QKVO + KD * WN * 3 + DV * WN + WN * WN + WN) * 4;
    cudaFuncSetAttribute(attn_kernel, cudaFuncAttributeMaxDynamicSharedMemorySize, smem);
    attn_kernel<<<NWIN, 256, smem>>>(pB, qkv_w, qkv_b, dwq_w7, dwq_b7, dwq_w5,
                                     dwq_b5, dwq_w3, dwq_b3, attn_b, pW);

    gemm_tc<1, 2><<<gN392_4, 256>>>(proj_w, proj_b, pW, pB, pC, 512, 512);
    dwconv_res_kernel<<<eb, 256>>>(pC, dw1_w, dw1_b, pD);
    gemm_tc<0, 0><<<gN392_8, 256>>>(ffn1_w1, ffn1_b1, pD, nullptr, pH, 1024, 512);
    gemm_tc<0, 1><<<gN392_4, 256>>>(ffn1_w2, ffn1_b2, pH, pD, out, 512, 1024);
}